// round 14
// baseline (speedup 1.0000x reference)
#include <cuda_runtime.h>
#include <cuda_fp16.h>
#include <cstdint>
#include <cstddef>

#define DEVINL __device__ __forceinline__

// fp16 scratch (static device allocations are allowed)
__device__ __half g_xh[4096 * 4096];     // x           [4096 x 4096]
__device__ __half g_wh[4096 * 5 * 256];  // weight flat [20480 x 256]
__device__ __half g_w1h[256 * 4096];     // w1          [256 x 4096]
__device__ __half g_w2h[4096 * 256];     // w2          [4096 x 256]
__device__ __half g_th[4096 * 256];      // t = x@w1^T  [4096 x 256]

// ---- single fused f32 -> f16 conversion over all four tensors ----
#define N4_X  4194304   // 4096*4096/4
#define N4_W  1310720   // 4096*5*256/4
#define N4_W1 262144    // 256*4096/4
#define N4_W2 262144    // 4096*256/4
#define N4_TOTAL (N4_X + N4_W + N4_W1 + N4_W2)

DEVINL void cvt_one(const float4* __restrict__ s, uint2* __restrict__ d, int i) {
    float4 v = s[i];
    __half2 h0 = __floats2half2_rn(v.x, v.y);
    __half2 h1 = __floats2half2_rn(v.z, v.w);
    uint2 r;
    r.x = *reinterpret_cast<uint32_t*>(&h0);
    r.y = *reinterpret_cast<uint32_t*>(&h1);
    d[i] = r;
}

__global__ void __launch_bounds__(256)
f2h_all(const float4* __restrict__ x,  uint2* __restrict__ xh,
        const float4* __restrict__ w,  uint2* __restrict__ wh,
        const float4* __restrict__ w1, uint2* __restrict__ w1h,
        const float4* __restrict__ w2, uint2* __restrict__ w2h) {
    const int stride = gridDim.x * blockDim.x;
    int i = blockIdx.x * blockDim.x + threadIdx.x;
#pragma unroll 8
    for (; i < N4_TOTAL; i += stride) {
        if (i < N4_X) {
            cvt_one(x, xh, i);
        } else if (i < N4_X + N4_W) {
            cvt_one(w, wh, i - N4_X);
        } else if (i < N4_X + N4_W + N4_W1) {
            cvt_one(w1, w1h, i - (N4_X + N4_W));
        } else {
            cvt_one(w2, w2h, i - (N4_X + N4_W + N4_W1));
        }
    }
}

DEVINL uint32_t smem_u32(const void* p) {
    return (uint32_t)__cvta_generic_to_shared(p);
}

DEVINL void ldsm_x4(uint32_t addr, uint32_t& r0, uint32_t& r1, uint32_t& r2, uint32_t& r3) {
    asm volatile("ldmatrix.sync.aligned.m8n8.x4.shared.b16 {%0,%1,%2,%3}, [%4];"
                 : "=r"(r0), "=r"(r1), "=r"(r2), "=r"(r3)
                 : "r"(addr));
}

DEVINL void mma_f16(float c[4], const uint32_t a[4], const uint32_t b[2]) {
    asm volatile(
        "mma.sync.aligned.m16n8k16.row.col.f32.f16.f16.f32 "
        "{%0,%1,%2,%3}, {%4,%5,%6,%7}, {%8,%9}, {%0,%1,%2,%3};"
        : "+f"(c[0]), "+f"(c[1]), "+f"(c[2]), "+f"(c[3])
        : "r"(a[0]), "r"(a[1]), "r"(a[2]), "r"(a[3]), "r"(b[0]), "r"(b[1]));
}

DEVINL void cp16(uint32_t saddr, const void* g) {
    asm volatile("cp.async.ca.shared.global [%0], [%1], 16;" :: "r"(saddr), "l"(g));
}
DEVINL void cp_commit() { asm volatile("cp.async.commit_group;" ::: "memory"); }
template <int N>
DEVINL void cp_wait() { asm volatile("cp.async.wait_group %0;" :: "n"(N) : "memory"); }

// Segmented fp16 NT GEMM. STAGES selectable (2 or 3), BK=64, 1 sync/iter,
// precomputed LDSM bases, bias staged through smem. Lean registers.
// MODE 0: t = x @ w1^T  (writes g_th, half).
// MODE 1: out = bias + t @ w2_ob^T + butterfly (writes f32 out).
template <int BM, int BN, int WARPS_M, int WARPS_N, int NSEG, int KSEG,
          int STAGES, int MODE, int MAXCTA>
__global__ void __launch_bounds__(WARPS_M * WARPS_N * 32, MAXCTA)
gemm_f16_seg(const float* __restrict__ bias,
             const int* __restrict__ flat,
             float* __restrict__ out) {
    constexpr int THREADS = WARPS_M * WARPS_N * 32;
    constexpr int BK = 64;
    constexpr int SROW = 72;              // halfs per smem row (64 data + 8 pad)
    constexpr int MT = (BM / WARPS_M) / 16;
    constexpr int NT = (BN / WARPS_N) / 8;
    constexpr int KPS = KSEG / BK;
    constexpr int KT = NSEG * KPS;
    constexpr int LDB = (MODE == 0) ? 4096 : 256;
    constexpr uint32_t A_STAGE_B = BM * SROW * 2;
    constexpr uint32_t B_STAGE_B = BN * SROW * 2;

    extern __shared__ char smem[];
    const __half** sAp = (const __half**)(smem);        // [NSEG]
    const __half** sBp = (const __half**)(smem + 64);   // [NSEG]
    int* sLda = (int*)(smem + 128);
    float* sBias = (float*)(smem + 256);                 // [BN] (MODE 1)
    __half* sAraw = (__half*)(smem + 256 + (MODE == 1 ? BN * 4 : 0));
    __half* sBraw = sAraw + STAGES * BM * SROW;

    const int tid = threadIdx.x;
    const int m0 = blockIdx.x * BM;
    const int nb0 = blockIdx.y * BN;

    if (tid == 0) {
        if (MODE == 0) {
            sAp[0] = g_xh;  sLda[0] = 4096;
            sBp[0] = g_w1h + (size_t)nb0 * 4096;
        } else {
            const int ob = blockIdx.z;
            sAp[0] = g_th;  sLda[0] = 256;
            sBp[0] = g_w2h + (size_t)ob * 65536 + (size_t)nb0 * 256;
#pragma unroll
            for (int a = 0; a < 5; ++a) {
                int f = flat[ob * 5 + a];
                sAp[1 + a] = g_xh + (size_t)(f / 5) * 256;   sLda[1 + a] = 4096;
                sBp[1 + a] = g_wh + (size_t)f * 65536 + (size_t)nb0 * 256;
            }
        }
    }
    if (MODE == 1) {
        if (tid < BN) sBias[tid] = bias[blockIdx.z * 256 + nb0 + tid];
    }
    __syncthreads();

    const int lane = tid & 31;
    const int warp = tid >> 5;
    const int wm0 = (warp % WARPS_M) * (BM / WARPS_M);
    const int wn0 = (warp / WARPS_M) * (BN / WARPS_N);

    // ldmatrix x4 per-lane addressing (same pattern for A and B fragments)
    const int rowL = lane & 15;
    const int colL = (lane >> 4) * 8;

    // Precomputed LDSM base addresses (stage 0, k-step 0)
    uint32_t aA[MT], aB[NT / 2];
#pragma unroll
    for (int mt = 0; mt < MT; ++mt)
        aA[mt] = smem_u32(sAraw + (wm0 + mt * 16 + rowL) * SROW + colL);
#pragma unroll
    for (int p = 0; p < NT / 2; ++p)
        aB[p] = smem_u32(sBraw + (wn0 + p * 16 + rowL) * SROW + colL);

    float acc[MT][NT][4] = {};

    auto load_tile = [&](int kt) {
        const int buf = kt % STAGES;
        const int seg = kt / KPS;
        const int kin = (kt - seg * KPS) * BK;
        const __half* Ab = sAp[seg];
        const __half* Bb = sBp[seg];
        const int lda = sLda[seg];
        __half* sA = sAraw + buf * BM * SROW;
        __half* sB = sBraw + buf * BN * SROW;
        constexpr int TOTAL = (BM + BN) * 8;          // 16B (8-half) chunks
#pragma unroll
        for (int c = 0; c < TOTAL / THREADS; ++c) {
            int idx = tid + c * THREADS;
            if (idx < BM * 8) {
                int r = idx >> 3, ch = idx & 7;
                cp16(smem_u32(&sA[r * SROW + ch * 8]),
                     Ab + (size_t)(m0 + r) * lda + kin + ch * 8);
            } else {
                int j = idx - BM * 8;
                int r = j >> 3, ch = j & 7;
                cp16(smem_u32(&sB[r * SROW + ch * 8]),
                     Bb + (size_t)r * LDB + kin + ch * 8);
            }
        }
        cp_commit();
    };

    auto compute = [&](int kt) {
        const uint32_t aoff = (uint32_t)(kt % STAGES) * A_STAGE_B;
        const uint32_t boff = (uint32_t)(kt % STAGES) * B_STAGE_B;
#pragma unroll
        for (int kk = 0; kk < BK / 16; ++kk) {
            uint32_t a[MT][4];
#pragma unroll
            for (int mt = 0; mt < MT; ++mt)
                ldsm_x4(aA[mt] + aoff + kk * 32, a[mt][0], a[mt][1], a[mt][2], a[mt][3]);
            uint32_t b[NT][2];
#pragma unroll
            for (int p = 0; p < NT / 2; ++p) {
                uint32_t r0, r1, r2, r3;
                ldsm_x4(aB[p] + boff + kk * 32, r0, r1, r2, r3);
                b[2 * p][0] = r0;  b[2 * p + 1][0] = r1;
                b[2 * p][1] = r2;  b[2 * p + 1][1] = r3;
            }
#pragma unroll
            for (int mt = 0; mt < MT; ++mt)
#pragma unroll
                for (int nt = 0; nt < NT; ++nt)
                    mma_f16(acc[mt][nt], a[mt], b[nt]);
        }
    };

    load_tile(0);
    if (STAGES >= 3) load_tile(1);

#pragma unroll 1
    for (int kt = 0; kt < KT; ++kt) {
        if (STAGES == 2) {
            cp_wait<0>();                     // drain: stage kt data ready
            __syncthreads();                  // compute(kt-1) retired -> buf reusable
            if (kt + 1 < KT) load_tile(kt + 1);
        } else {
            if (kt == KT - 1) { cp_wait<0>(); } else { cp_wait<1>(); }
            __syncthreads();
            if (kt + 2 < KT) load_tile(kt + 2);
        }
        compute(kt);
    }

    // Epilogue
#pragma unroll
    for (int mt = 0; mt < MT; ++mt) {
        const int row = m0 + wm0 + mt * 16 + (lane >> 2);
#pragma unroll
        for (int nt = 0; nt < NT; ++nt) {
            const int coll = wn0 + nt * 8 + (lane & 3) * 2;
            if (MODE == 0) {
                const int col = nb0 + coll;
                *(__half2*)(g_th + (size_t)row * 256 + col)
                    = __floats2half2_rn(acc[mt][nt][0], acc[mt][nt][1]);
                *(__half2*)(g_th + (size_t)(row + 8) * 256 + col)
                    = __floats2half2_rn(acc[mt][nt][2], acc[mt][nt][3]);
            } else {
                const int col = blockIdx.z * 256 + nb0 + coll;
                float b0 = sBias[coll];
                float b1 = sBias[coll + 1];
                *reinterpret_cast<float2*>(&out[(size_t)row * 4096 + col])
                    = make_float2(acc[mt][nt][0] + b0, acc[mt][nt][1] + b1);
                *reinterpret_cast<float2*>(&out[(size_t)(row + 8) * 4096 + col])
                    = make_float2(acc[mt][nt][2] + b0, acc[mt][nt][3] + b1);
            }
        }
    }
}

extern "C" void kernel_launch(void* const* d_in, const int* in_sizes, int n_in,
                              void* d_out, int out_size) {
    (void)in_sizes; (void)n_in; (void)out_size;
    const float* x      = (const float*)d_in[0];
    const float* weight = (const float*)d_in[1];
    const float* w1     = (const float*)d_in[2];
    const float* w2     = (const float*)d_in[3];
    const float* bias   = (const float*)d_in[4];
    const int*   flat   = (const int*)d_in[5];
    float* out = (float*)d_out;

    // ---- one fused f32 -> f16 conversion launch ----
    __half *xh, *wh, *w1h, *w2h;
    cudaGetSymbolAddress((void**)&xh,  g_xh);
    cudaGetSymbolAddress((void**)&wh,  g_wh);
    cudaGetSymbolAddress((void**)&w1h, g_w1h);
    cudaGetSymbolAddress((void**)&w2h, g_w2h);

    f2h_all<<<1184, 256>>>((const float4*)x,      (uint2*)xh,
                           (const float4*)weight, (uint2*)wh,
                           (const float4*)w1,     (uint2*)w1h,
                           (const float4*)w2,     (uint2*)w2h);

    // ---- Kernel A: t = x @ w1^T  (M=4096, N=256, K=4096) ----
    // BM=64, BN=64, warps 2x2 (128 thr), 3-stage, grid (64,4) = 256 CTAs, 4 CTAs/SM
    constexpr int SMEM_A = 256 + 3 * (64 + 64) * 72 * 2;            // 55,552 B
    // ---- Kernel B: BM=128, BN=128, warps 4x2 (256 thr), warp tile 32x64,
    //      3-stage lean (110.9 KB), MAXCTA=2 -> 2 CTAs/SM (221.8 KB < 228 KB)
    constexpr int SMEM_B = 256 + 128 * 4 + 3 * (128 + 128) * 72 * 2; // 111,360 B

    cudaFuncSetAttribute(gemm_f16_seg<64, 64, 2, 2, 1, 4096, 3, 0, 4>,
                         cudaFuncAttributeMaxDynamicSharedMemorySize, SMEM_A);
    cudaFuncSetAttribute(gemm_f16_seg<128, 128, 4, 2, 6, 256, 3, 1, 2>,
                         cudaFuncAttributeMaxDynamicSharedMemorySize, SMEM_B);

    gemm_f16_seg<64, 64, 2, 2, 1, 4096, 3, 0, 4>
        <<<dim3(64, 4, 1), 128, SMEM_A>>>(bias, flat, out);

    gemm_f16_seg<128, 128, 4, 2, 6, 256, 3, 1, 2>
        <<<dim3(32, 2, 16), 256, SMEM_B>>>(bias, flat, out);
}

// round 15
// speedup vs baseline: 1.0898x; 1.0898x over previous
#include <cuda_runtime.h>
#include <cuda_fp16.h>
#include <cstdint>
#include <cstddef>

#define DEVINL __device__ __forceinline__

// fp16 scratch (static device allocations are allowed)
__device__ __half g_xh[4096 * 4096];     // x           [4096 x 4096]
__device__ __half g_wh[4096 * 5 * 256];  // weight flat [20480 x 256]
__device__ __half g_w1h[256 * 4096];     // w1          [256 x 4096]
__device__ __half g_w2h[4096 * 256];     // w2          [4096 x 256]
__device__ __half g_th[4096 * 256];      // t = x@w1^T  [4096 x 256]

// ---- single fused f32 -> f16 conversion over all four tensors ----
#define N4_X  4194304   // 4096*4096/4
#define N4_W  1310720   // 4096*5*256/4
#define N4_W1 262144    // 256*4096/4
#define N4_W2 262144    // 4096*256/4
#define N4_TOTAL (N4_X + N4_W + N4_W1 + N4_W2)

DEVINL void cvt_one(const float4* __restrict__ s, uint2* __restrict__ d, int i) {
    float4 v = s[i];
    __half2 h0 = __floats2half2_rn(v.x, v.y);
    __half2 h1 = __floats2half2_rn(v.z, v.w);
    uint2 r;
    r.x = *reinterpret_cast<uint32_t*>(&h0);
    r.y = *reinterpret_cast<uint32_t*>(&h1);
    d[i] = r;
}

__global__ void __launch_bounds__(256)
f2h_all(const float4* __restrict__ x,  uint2* __restrict__ xh,
        const float4* __restrict__ w,  uint2* __restrict__ wh,
        const float4* __restrict__ w1, uint2* __restrict__ w1h,
        const float4* __restrict__ w2, uint2* __restrict__ w2h) {
    const int stride = gridDim.x * blockDim.x;
    int i = blockIdx.x * blockDim.x + threadIdx.x;
#pragma unroll 8
    for (; i < N4_TOTAL; i += stride) {
        if (i < N4_X) {
            cvt_one(x, xh, i);
        } else if (i < N4_X + N4_W) {
            cvt_one(w, wh, i - N4_X);
        } else if (i < N4_X + N4_W + N4_W1) {
            cvt_one(w1, w1h, i - (N4_X + N4_W));
        } else {
            cvt_one(w2, w2h, i - (N4_X + N4_W + N4_W1));
        }
    }
}

DEVINL uint32_t smem_u32(const void* p) {
    return (uint32_t)__cvta_generic_to_shared(p);
}

DEVINL void ldsm_x4(uint32_t addr, uint32_t& r0, uint32_t& r1, uint32_t& r2, uint32_t& r3) {
    asm volatile("ldmatrix.sync.aligned.m8n8.x4.shared.b16 {%0,%1,%2,%3}, [%4];"
                 : "=r"(r0), "=r"(r1), "=r"(r2), "=r"(r3)
                 : "r"(addr));
}

DEVINL void mma_f16(float c[4], const uint32_t a[4], const uint32_t b[2]) {
    asm volatile(
        "mma.sync.aligned.m16n8k16.row.col.f32.f16.f16.f32 "
        "{%0,%1,%2,%3}, {%4,%5,%6,%7}, {%8,%9}, {%0,%1,%2,%3};"
        : "+f"(c[0]), "+f"(c[1]), "+f"(c[2]), "+f"(c[3])
        : "r"(a[0]), "r"(a[1]), "r"(a[2]), "r"(a[3]), "r"(b[0]), "r"(b[1]));
}

DEVINL void cp16(uint32_t saddr, const void* g) {
    asm volatile("cp.async.ca.shared.global [%0], [%1], 16;" :: "r"(saddr), "l"(g));
}
DEVINL void cp_commit() { asm volatile("cp.async.commit_group;" ::: "memory"); }
template <int N>
DEVINL void cp_wait() { asm volatile("cp.async.wait_group %0;" :: "n"(N) : "memory"); }

// Segmented fp16 NT GEMM. STAGES selectable (2 or 3), BK=64, 1 sync/iter,
// precomputed LDSM bases, bias staged through smem. Lean registers.
// MODE 0: t = x @ w1^T  (writes g_th, half).
// MODE 1: out = bias + t @ w2_ob^T + butterfly (writes f32 out).
template <int BM, int BN, int WARPS_M, int WARPS_N, int NSEG, int KSEG,
          int STAGES, int MODE, int MAXCTA>
__global__ void __launch_bounds__(WARPS_M * WARPS_N * 32, MAXCTA)
gemm_f16_seg(const float* __restrict__ bias,
             const int* __restrict__ flat,
             float* __restrict__ out) {
    constexpr int THREADS = WARPS_M * WARPS_N * 32;
    constexpr int BK = 64;
    constexpr int SROW = 72;              // halfs per smem row (64 data + 8 pad)
    constexpr int MT = (BM / WARPS_M) / 16;
    constexpr int NT = (BN / WARPS_N) / 8;
    constexpr int KPS = KSEG / BK;
    constexpr int KT = NSEG * KPS;
    constexpr int LDB = (MODE == 0) ? 4096 : 256;
    constexpr uint32_t A_STAGE_B = BM * SROW * 2;
    constexpr uint32_t B_STAGE_B = BN * SROW * 2;

    extern __shared__ char smem[];
    const __half** sAp = (const __half**)(smem);        // [NSEG]
    const __half** sBp = (const __half**)(smem + 64);   // [NSEG]
    int* sLda = (int*)(smem + 128);
    float* sBias = (float*)(smem + 256);                 // [BN] (MODE 1)
    __half* sAraw = (__half*)(smem + 256 + (MODE == 1 ? BN * 4 : 0));
    __half* sBraw = sAraw + STAGES * BM * SROW;

    const int tid = threadIdx.x;
    const int m0 = blockIdx.x * BM;
    const int nb0 = blockIdx.y * BN;

    if (tid == 0) {
        if (MODE == 0) {
            sAp[0] = g_xh;  sLda[0] = 4096;
            sBp[0] = g_w1h + (size_t)nb0 * 4096;
        } else {
            const int ob = blockIdx.z;
            sAp[0] = g_th;  sLda[0] = 256;
            sBp[0] = g_w2h + (size_t)ob * 65536 + (size_t)nb0 * 256;
#pragma unroll
            for (int a = 0; a < 5; ++a) {
                int f = flat[ob * 5 + a];
                sAp[1 + a] = g_xh + (size_t)(f / 5) * 256;   sLda[1 + a] = 4096;
                sBp[1 + a] = g_wh + (size_t)f * 65536 + (size_t)nb0 * 256;
            }
        }
    }
    if (MODE == 1) {
        if (tid < BN) sBias[tid] = bias[blockIdx.z * 256 + nb0 + tid];
    }
    __syncthreads();

    const int lane = tid & 31;
    const int warp = tid >> 5;
    const int wm0 = (warp % WARPS_M) * (BM / WARPS_M);
    const int wn0 = (warp / WARPS_M) * (BN / WARPS_N);

    // ldmatrix x4 per-lane addressing (same pattern for A and B fragments)
    const int rowL = lane & 15;
    const int colL = (lane >> 4) * 8;

    // Precomputed LDSM base addresses (stage 0, k-step 0)
    uint32_t aA[MT], aB[NT / 2];
#pragma unroll
    for (int mt = 0; mt < MT; ++mt)
        aA[mt] = smem_u32(sAraw + (wm0 + mt * 16 + rowL) * SROW + colL);
#pragma unroll
    for (int p = 0; p < NT / 2; ++p)
        aB[p] = smem_u32(sBraw + (wn0 + p * 16 + rowL) * SROW + colL);

    float acc[MT][NT][4] = {};

    auto load_tile = [&](int kt) {
        const int buf = kt % STAGES;
        const int seg = kt / KPS;
        const int kin = (kt - seg * KPS) * BK;
        const __half* Ab = sAp[seg];
        const __half* Bb = sBp[seg];
        const int lda = sLda[seg];
        __half* sA = sAraw + buf * BM * SROW;
        __half* sB = sBraw + buf * BN * SROW;
        constexpr int TOTAL = (BM + BN) * 8;          // 16B (8-half) chunks
#pragma unroll
        for (int c = 0; c < TOTAL / THREADS; ++c) {
            int idx = tid + c * THREADS;
            if (idx < BM * 8) {
                int r = idx >> 3, ch = idx & 7;
                cp16(smem_u32(&sA[r * SROW + ch * 8]),
                     Ab + (size_t)(m0 + r) * lda + kin + ch * 8);
            } else {
                int j = idx - BM * 8;
                int r = j >> 3, ch = j & 7;
                cp16(smem_u32(&sB[r * SROW + ch * 8]),
                     Bb + (size_t)r * LDB + kin + ch * 8);
            }
        }
        cp_commit();
    };

    auto compute = [&](int kt) {
        const uint32_t aoff = (uint32_t)(kt % STAGES) * A_STAGE_B;
        const uint32_t boff = (uint32_t)(kt % STAGES) * B_STAGE_B;
#pragma unroll
        for (int kk = 0; kk < BK / 16; ++kk) {
            uint32_t a[MT][4];
#pragma unroll
            for (int mt = 0; mt < MT; ++mt)
                ldsm_x4(aA[mt] + aoff + kk * 32, a[mt][0], a[mt][1], a[mt][2], a[mt][3]);
            uint32_t b[NT][2];
#pragma unroll
            for (int p = 0; p < NT / 2; ++p) {
                uint32_t r0, r1, r2, r3;
                ldsm_x4(aB[p] + boff + kk * 32, r0, r1, r2, r3);
                b[2 * p][0] = r0;  b[2 * p + 1][0] = r1;
                b[2 * p][1] = r2;  b[2 * p + 1][1] = r3;
            }
#pragma unroll
            for (int mt = 0; mt < MT; ++mt)
#pragma unroll
                for (int nt = 0; nt < NT; ++nt)
                    mma_f16(acc[mt][nt], a[mt], b[nt]);
        }
    };

    load_tile(0);
    if (STAGES >= 3) load_tile(1);

#pragma unroll 1
    for (int kt = 0; kt < KT; ++kt) {
        if (STAGES == 2) {
            cp_wait<0>();                     // drain: stage kt data ready
            __syncthreads();                  // compute(kt-1) retired -> buf reusable
            if (kt + 1 < KT) load_tile(kt + 1);
        } else {
            if (kt == KT - 1) { cp_wait<0>(); } else { cp_wait<1>(); }
            __syncthreads();
            if (kt + 2 < KT) load_tile(kt + 2);
        }
        compute(kt);
    }

    // Epilogue
#pragma unroll
    for (int mt = 0; mt < MT; ++mt) {
        const int row = m0 + wm0 + mt * 16 + (lane >> 2);
#pragma unroll
        for (int nt = 0; nt < NT; ++nt) {
            const int coll = wn0 + nt * 8 + (lane & 3) * 2;
            if (MODE == 0) {
                const int col = nb0 + coll;
                *(__half2*)(g_th + (size_t)row * 256 + col)
                    = __floats2half2_rn(acc[mt][nt][0], acc[mt][nt][1]);
                *(__half2*)(g_th + (size_t)(row + 8) * 256 + col)
                    = __floats2half2_rn(acc[mt][nt][2], acc[mt][nt][3]);
            } else {
                const int col = blockIdx.z * 256 + nb0 + coll;
                float b0 = sBias[coll];
                float b1 = sBias[coll + 1];
                *reinterpret_cast<float2*>(&out[(size_t)row * 4096 + col])
                    = make_float2(acc[mt][nt][0] + b0, acc[mt][nt][1] + b1);
                *reinterpret_cast<float2*>(&out[(size_t)(row + 8) * 4096 + col])
                    = make_float2(acc[mt][nt][2] + b0, acc[mt][nt][3] + b1);
            }
        }
    }
}

extern "C" void kernel_launch(void* const* d_in, const int* in_sizes, int n_in,
                              void* d_out, int out_size) {
    (void)in_sizes; (void)n_in; (void)out_size;
    const float* x      = (const float*)d_in[0];
    const float* weight = (const float*)d_in[1];
    const float* w1     = (const float*)d_in[2];
    const float* w2     = (const float*)d_in[3];
    const float* bias   = (const float*)d_in[4];
    const int*   flat   = (const int*)d_in[5];
    float* out = (float*)d_out;

    // ---- one fused f32 -> f16 conversion launch ----
    __half *xh, *wh, *w1h, *w2h;
    cudaGetSymbolAddress((void**)&xh,  g_xh);
    cudaGetSymbolAddress((void**)&wh,  g_wh);
    cudaGetSymbolAddress((void**)&w1h, g_w1h);
    cudaGetSymbolAddress((void**)&w2h, g_w2h);

    f2h_all<<<1184, 256>>>((const float4*)x,      (uint2*)xh,
                           (const float4*)weight, (uint2*)wh,
                           (const float4*)w1,     (uint2*)w1h,
                           (const float4*)w2,     (uint2*)w2h);

    // ---- Kernel A: t = x @ w1^T  (M=4096, N=256, K=4096) ----
    // BM=64, BN=64, warps 2x2 (128 thr), 2-stage lean (37.1 KB), MAXCTA=5
    // -> 5 CTAs/SM = 20 warps/SM, all 256 CTAs resident in one wave
    constexpr int SMEM_A = 256 + 2 * (64 + 64) * 72 * 2;            // 37,120 B
    // ---- Kernel B (R13 exact): BM=128, BN=128, warps 4x2 (256 thr),
    //      2-stage lean (74.5 KB), MAXCTA=2 -> 16 warps/SM
    constexpr int SMEM_B = 256 + 128 * 4 + 2 * (128 + 128) * 72 * 2; // 74,496 B

    cudaFuncSetAttribute(gemm_f16_seg<64, 64, 2, 2, 1, 4096, 2, 0, 5>,
                         cudaFuncAttributeMaxDynamicSharedMemorySize, SMEM_A);
    cudaFuncSetAttribute(gemm_f16_seg<128, 128, 4, 2, 6, 256, 2, 1, 2>,
                         cudaFuncAttributeMaxDynamicSharedMemorySize, SMEM_B);

    gemm_f16_seg<64, 64, 2, 2, 1, 4096, 2, 0, 5>
        <<<dim3(64, 4, 1), 128, SMEM_A>>>(bias, flat, out);

    gemm_f16_seg<128, 128, 4, 2, 6, 256, 2, 1, 2>
        <<<dim3(32, 2, 16), 256, SMEM_B>>>(bias, flat, out);
}